// round 14
// baseline (speedup 1.0000x reference)
#include <cuda_runtime.h>
#include <math.h>

#define NB 16
#define NT 50
#define NA 3
#define NG 76
#define PLANE 5776
#define NC 85
#define CH 255
#define NBT 800
#define CELL_WORDS 181
#define TOTAL_CONF 277248
#define THREADS 512
#define DENSE_BLOCKS 48          // one conf plane per dense block
#define GRID 64                  // 48 dense + 16 builders
#define PLANE4 1444

// ---------------- device scratch (combiner resets everything) ----------------
__device__ float g_acc[8];   // sx, sy, sw, sh, sobj, nm, mcc, nz
__device__ float g_dsum;     // dense softplus sum minus all corrections
__device__ int   g_done;

__device__ __forceinline__ float softplus_f(float v) {
    float a = fabsf(v);
    return fmaxf(v, 0.f) + __logf(1.f + __expf(-a));
}

__device__ __forceinline__ float block_reduce512(float v, float* sh) {
    int lane = threadIdx.x & 31, wid = threadIdx.x >> 5;
    #pragma unroll
    for (int o = 16; o; o >>= 1) v += __shfl_down_sync(0xffffffffu, v, o);
    if (lane == 0) sh[wid] = v;
    __syncthreads();
    if (wid == 0) {
        v = (lane < 16) ? sh[lane] : 0.f;
        #pragma unroll
        for (int o = 8; o; o >>= 1) v += __shfl_down_sync(0xffffffffu, v, o);
    }
    __syncthreads();
    return v;   // valid in thread 0
}

__global__ __launch_bounds__(THREADS)
void k_yolo(const float* __restrict__ sample,
            const float* __restrict__ targets,
            const float* __restrict__ anchors,
            float* __restrict__ out)
{
    __shared__ unsigned s_zero[CELL_WORDS];
    __shared__ int      s_key[NT];
    __shared__ float    s_g4[NT][4];
    __shared__ float    s_accw[16][9];
    __shared__ float    s_red[16];
    __shared__ float    s_f[9];
    __shared__ int      s_flag;

    const int tid = threadIdx.x;
    const int blk = blockIdx.x;

    if (blk < DENSE_BLOCKS) {
        // ---- dense block = one conf plane: 3 constant-offset loads, one round ----
        const float4* c4 = (const float4*)sample + (size_t)(85 * blk + 4) * PLANE4;
        float4 v0 = c4[tid];
        float4 v1 = c4[tid + THREADS];
        bool h3 = (tid + 2 * THREADS) < PLANE4;        // 420 threads take a 3rd
        float4 v2 = h3 ? c4[tid + 2 * THREADS] : make_float4(0.f, 0.f, 0.f, 0.f);

        float s = fmaxf(v0.x,0.f) + fmaxf(v0.y,0.f) + fmaxf(v0.z,0.f) + fmaxf(v0.w,0.f)
                + fmaxf(v1.x,0.f) + fmaxf(v1.y,0.f) + fmaxf(v1.z,0.f) + fmaxf(v1.w,0.f);
        float p0 = (1.f + __expf(-fabsf(v0.x))) * (1.f + __expf(-fabsf(v0.y)))
                 * (1.f + __expf(-fabsf(v0.z))) * (1.f + __expf(-fabsf(v0.w)));
        float p1 = (1.f + __expf(-fabsf(v1.x))) * (1.f + __expf(-fabsf(v1.y)))
                 * (1.f + __expf(-fabsf(v1.z))) * (1.f + __expf(-fabsf(v1.w)));
        s += __logf(p0) + __logf(p1);
        if (h3) {
            float s2 = fmaxf(v2.x,0.f) + fmaxf(v2.y,0.f) + fmaxf(v2.z,0.f) + fmaxf(v2.w,0.f);
            float p2 = (1.f + __expf(-fabsf(v2.x))) * (1.f + __expf(-fabsf(v2.y)))
                     * (1.f + __expf(-fabsf(v2.z))) * (1.f + __expf(-fabsf(v2.w)));
            s += s2 + __logf(p2);
        }
        float rs = block_reduce512(s, s_red);
        if (tid == 0) atomicAdd(&g_dsum, rs);
    } else {
        // ------------- builder block for batch b (identical to R13) -------------
        const int b = blk - DENSE_BLOCKS;
        float awS[NA], ahS[NA];
        #pragma unroll
        for (int a = 0; a < NA; a++) {
            awS[a] = anchors[2*a]   * 0.125f;   // /8 (stride = 608/76)
            ahS[a] = anchors[2*a+1] * 0.125f;
        }
        if (tid < CELL_WORDS) s_zero[tid] = 0u;

        int   cellC[2], bnC[2];
        bool  ignC[2], actC[2];
        float gxC[2], gyC[2], gwC[2], ghC[2];
        #pragma unroll
        for (int c = 0; c < 2; c++) {
            int t = tid + c * THREADS;
            actC[c] = (t < NBT);
            ignC[c] = false; cellC[c] = 0; bnC[c] = 0;
            gxC[c] = gyC[c] = gwC[c] = ghC[c] = 0.f;
            if (actC[c]) {
                int bt = t / NT;
                const float* tg = targets + (size_t)t * 5;
                const float* t0 = targets + (size_t)(bt * NT) * 5;
                float s5 = tg[0] + tg[1] + tg[2] + tg[3] + tg[4];
                bool mm = s5 > 0.f;
                float gx = (mm ? tg[1] : t0[1]) * NG;
                float gy = (mm ? tg[2] : t0[2]) * NG;
                float gw = (mm ? tg[3] : t0[3]) * NG;
                float gh = (mm ? tg[4] : t0[4]) * NG;
                float best = -1e30f; int bn = 0; bool ign = false;
                #pragma unroll
                for (int a = 0; a < NA; a++) {
                    float iw = fminf(gw, awS[a]) + 1.f;
                    float ih = fminf(gh, ahS[a]) + 1.f;
                    float inter = fmaxf(iw, 0.f) * fmaxf(ih, 0.f);
                    float denom = (gw + 1.f) * (gh + 1.f)
                                + (awS[a] + 1.f) * (ahS[a] + 1.f) - inter + 1e-12f;
                    float iou = __fdividef(inter, denom);
                    ign |= (iou > 0.5f);
                    if (iou > best) { best = iou; bn = a; }   // first-max ties
                }
                gxC[c] = gx; gyC[c] = gy; gwC[c] = gw; ghC[c] = gh;
                bnC[c] = bn; ignC[c] = ign;
                cellC[c] = ((int)gy) * NG + (int)gx;
            }
        }
        __syncthreads();   // s_zero zeroing complete

        #pragma unroll
        for (int c = 0; c < 2; c++) {
            int t = tid + c * THREADS;
            if (actC[c]) {
                if (ignC[c])
                    atomicOr(&s_zero[cellC[c] >> 5], 1u << (cellC[c] & 31));
                int lo = b * NT;
                if (t >= lo && t < lo + NT) {      // own-batch target
                    int ti = t - lo;
                    s_key[ti] = bnC[c] * PLANE + cellC[c];
                    s_g4[ti][0] = gxC[c]; s_g4[ti][1] = gyC[c];
                    s_g4[ti][2] = gwC[c]; s_g4[ti][3] = ghC[c];
                }
            }
        }
        __syncthreads();   // union + keys complete

        float acc[9];        // 8 sparse fields + [8] = correction sum
        #pragma unroll
        for (int c = 0; c < 9; c++) acc[c] = 0.f;

        if (tid < NT) {
            int mykey = s_key[tid];
            bool winner = true;                   // last-wins scan
            #pragma unroll
            for (int t2 = 0; t2 < NT; t2++)
                winner &= !((t2 > tid) & (s_key[t2] == mykey));
            if (winner) {
                int cell = mykey % PLANE;
                int bn   = mykey / PLANE;
                float gx = s_g4[tid][0], gy = s_g4[tid][1];
                float gw = s_g4[tid][2], gh = s_g4[tid][3];
                int gi = (int)gx, gj = (int)gy;
                size_t poff = ((size_t)(b * CH + bn * NC)) * PLANE + (size_t)cell;
                float p0 = sample[poff];
                float p1 = sample[poff + 1 * PLANE];
                float p2 = sample[poff + 2 * PLANE];
                float p3 = sample[poff + 3 * PLANE];
                float p4 = sample[poff + 4 * PLANE];

                float x  = __fdividef(1.f, 1.f + __expf(-p0));
                float y  = __fdividef(1.f, 1.f + __expf(-p1));
                float pc = __fdividef(1.f, 1.f + __expf(-p4));
                float tx = gx - (float)gi;
                float ty = gy - (float)gj;
                float tw = __logf(__fdividef(gw, awS[bn]) + 1e-16f);
                float th = __logf(__fdividef(gh, ahS[bn]) + 1e-16f);
                float dx = x - tx, dy = y - ty, dw = p2 - tw, dh = p3 - th;
                acc[0] = dx*dx; acc[1] = dy*dy; acc[2] = dw*dw; acc[3] = dh*dh;
                acc[4] = -__logf(pc + 1e-12f);
                acc[5] = 1.f;                                  // nm
                if (!((s_zero[cell >> 5] >> (cell & 31)) & 1u)) {
                    acc[6] = 1.f;                              // mcc
                    acc[8] = softplus_f(p4);                   // winner correction
                }
            }
        }

        // ignore-cell corrections straight off the bitmap; planes 3b..3b+2
        if (tid < CELL_WORDS) {
            unsigned w = s_zero[tid];
            if (b == 0) acc[7] = (float)__popc(w);             // nz (builder 0 only)
            while (w) {
                int bit = __ffs(w) - 1; w &= w - 1;
                int cell = tid * 32 + bit;
                #pragma unroll
                for (int pp = 0; pp < 3; pp++) {
                    int p = 3 * b + pp;
                    acc[8] += softplus_f(
                        sample[(size_t)(85 * p + 4) * PLANE + (size_t)cell]);
                }
            }
        }

        // single fused 9-field reduction, one barrier
        int lane = tid & 31, wid = tid >> 5;
        #pragma unroll
        for (int c = 0; c < 9; c++)
            #pragma unroll
            for (int o = 16; o; o >>= 1)
                acc[c] += __shfl_down_sync(0xffffffffu, acc[c], o);
        if (lane == 0)
            #pragma unroll
            for (int c = 0; c < 9; c++) s_accw[wid][c] = acc[c];
        __syncthreads();
        if (tid < 9) {
            float sum = 0.f;
            #pragma unroll
            for (int w = 0; w < 16; w++) sum += s_accw[w][tid];
            if (tid < 8) atomicAdd(&g_acc[tid], sum);
            else         atomicAdd(&g_dsum, -sum);     // corrections
        }
    }

    if (tid < 16) __threadfence();
    __syncthreads();

    // ---- single ticket; last block combines in one scalar round ----
    if (tid == 0)
        s_flag = (atomicAdd(&g_done, 1) == GRID - 1) ? 1 : 0;
    __syncthreads();
    if (s_flag) {
        __threadfence();
        if (tid < 8) s_f[tid] = g_acc[tid];
        if (tid == 8) s_f[8] = g_dsum;
        __syncthreads();
        if (tid < 8) g_acc[tid] = 0.f;        // reset for next replay
        if (tid == 8) g_dsum = 0.f;
        if (tid == 0) {
            float nm   = fmaxf(s_f[5], 1.f);
            float lx   = 2.0f * s_f[0] / nm;
            float ly   = 2.0f * s_f[1] / nm;
            float lw   = 1.6f * s_f[2] / nm;
            float lh   = 1.6f * s_f[3] / nm;
            float lobj = 1.0f * s_f[4] / nm;
            float ncnt = (float)TOTAL_CONF - 48.f * s_f[7] - s_f[6];
            float lnoobj = 0.5f * s_f[8] / fmaxf(ncnt, 1.f);
            out[0] = lx + ly + lw + lh + lnoobj + lobj;
            out[1] = lx; out[2] = ly; out[3] = lw; out[4] = lh;
            out[5] = lobj; out[6] = lnoobj;
            atomicExch(&g_done, 0);
        }
    }
}

extern "C" void kernel_launch(void* const* d_in, const int* in_sizes, int n_in,
                              void* d_out, int out_size)
{
    const float* sample  = (const float*)d_in[0];
    const float* targets = (const float*)d_in[1];
    const float* anchors = (const float*)d_in[2];
    float* out = (float*)d_out;

    k_yolo<<<GRID, THREADS>>>(sample, targets, anchors, out);
}